// round 14
// baseline (speedup 1.0000x reference)
#include <cuda_runtime.h>
#include <cuda_bf16.h>
#include <cstdint>

// N boxes (dynamic), C=256, G=7, fmap dims {38,19,10,5,3,1}
#define ROI_G    7
#define ROI_GG   49
#define ROI_EPB  12544          // 256*49
#define TF_TOTAL 496640         // sum over levels of D*D*256
#define MAXPB    5              // provable bound on short-axis patch size
#define MAXNR    35             // 7*MAXPB
#define RSTRIDE  257            // odd -> distinct rows hit distinct banks

#define SOUT_HALF   6272        // floats per half (128 ch * 49)
#define SOUT_BYTES  25088       // bytes per half (16B multiple)
#define DYN_SR_OFF  50176       // s_out[2][6272] bytes
#define DYN_SMEM    86160       // + s_r[35*257]*4 = 35980 -> padded

// Channel-last transposed fmaps: tf[level][x*D+y][c]  (1.99 MB, L2-resident)
static __device__ float tfmap[TF_TOTAL];

__constant__ int c_bnd[7] = {0, 369664, 462080, 487680, 494080, 496384, 496640};
__constant__ int c_Dc[6]  = {38, 19, 10, 5, 3, 1};

__device__ __forceinline__ uint32_t smem_u32(const void* p) {
    uint32_t a;
    asm("{ .reg .u64 t; cvta.to.shared.u64 t, %1; cvt.u32.u64 %0, t; }"
        : "=r"(a) : "l"(p));
    return a;
}

// ---------------------------------------------------------------------------
// Prep: transpose fmap[c][x][y] -> tfmap[(x*D+y)*256 + c].
// idx walks [level][c][xy] so READS are perfectly coalesced; the scatter is
// on the stores (fire-and-forget, no warp stall).
// ---------------------------------------------------------------------------
template <int D>
__device__ __forceinline__ void tpose_level(const float* __restrict__ f,
                                            int local, int base) {
    const int DD = D * D;
    const int c  = local / DD;           // compile-time D -> mul-by-reciprocal
    const int xy = local - c * DD;
    tfmap[base + (xy << 8) + c] = __ldg(f + local);
}

__global__ void prep_kernel(const float* __restrict__ f0, const float* __restrict__ f1,
                            const float* __restrict__ f2, const float* __restrict__ f3,
                            const float* __restrict__ f4, const float* __restrict__ f5) {
    int idx = blockIdx.x * blockDim.x + threadIdx.x;
    if (idx >= TF_TOTAL) return;
    int l = 0;
    #pragma unroll
    for (int j = 1; j < 6; ++j) l += (idx >= c_bnd[j]) ? 1 : 0;
    const int local = idx - c_bnd[l];
    const int base  = c_bnd[l];
    switch (l) {
        case 0: tpose_level<38>(f0, local, base); break;
        case 1: tpose_level<19>(f1, local, base); break;
        case 2: tpose_level<10>(f2, local, base); break;
        case 3: tpose_level<5>(f3, local, base); break;
        case 4: tpose_level<3>(f4, local, base); break;
        default: tpose_level<1>(f5, local, base); break;
    }
}

// ---------------------------------------------------------------------------
// Main: one block (512 thr) per box. Separable bilinear:
//  pass 1: long-axis lerp from tfmap (coalesced LDG.128) -> s_r[NR][256]
//  pass 2: short-axis lerp s_r -> s_out staging (conflict-free STS), then
//          cp.async.bulk store of 25088B per 128-channel half (double-
//          buffered; the DMA engine's aligned writes replace ~900 misaligned
//          STG wavefronts per box and overlap the other half's compute).
// ---------------------------------------------------------------------------
__global__ __launch_bounds__(512)
void roi_kernel(const float* __restrict__ boxes, float* __restrict__ out) {
    extern __shared__ char dyn[];
    float* s_out = (float*)dyn;                    // [2][6272]
    float* s_r   = (float*)(dyn + DYN_SR_OFF);     // [35*257]

    __shared__ int    s_o0[MAXNR], s_o1[MAXNR];
    __shared__ float  s_a0[MAXNR], s_a1[MAXNR];
    __shared__ float4 s_tab[ROI_GG];               // (w0, w1, r0_bits, r1_bits)
    __shared__ int    s_i0[14], s_i1[14];          // [0..6]=x, [7..13]=y
    __shared__ float  s_p0[14], s_p1[14];

    const int n = blockIdx.x;
    const int t = threadIdx.x;

    const float bx1 = __ldg(boxes + 4 * n + 0);
    const float by1 = __ldg(boxes + 4 * n + 1);
    const float bx2 = __ldg(boxes + 4 * n + 2);
    const float by2 = __ldg(boxes + 4 * n + 3);

    const float avg = sqrtf((bx2 - bx1) * (by2 - by1));
    int lvl = (int)floorf(5.0f + log2f(avg));
    lvl = max(0, min(5, lvl));
    const int D    = c_Dc[lvl];
    const int base = c_bnd[lvl];

    // 14 sample sets: floor/ceil indices + proportion weights (ref-exact)
    if (t < 14) {
        const int axis = t / 7, g = t - axis * 7;
        const float lo = axis ? by1 : bx1;
        const float hi = axis ? by2 : bx2;
        const float fr = fminf(fmaxf(lo + ((float)g * (hi - lo)) / 6.0f, 0.0f), 1.0f);
        const float u  = fr * (float)(D - 1);
        const float u0 = floorf(u);
        s_i0[t] = (int)u0;
        s_i1[t] = (int)ceilf(u);
        const float p0 = 1.0f - (u - u0);          // ddx==1 convention of ref
        s_p0[t] = p0;
        s_p1[t] = 1.0f - p0;
    }
    __syncthreads();

    // Meta, computed by every thread from smem broadcasts (no t==0 stage)
    const int PX  = s_i1[6]  - s_i0[0] + 1;
    const int PY  = s_i1[13] - s_i0[7] + 1;
    const int xf  = (PX >= PY) ? 1 : 0;            // lerp longer axis first
    const int blo = xf ? s_i0[7] : s_i0[0];        // short-axis patch start
    const int PB  = min(xf ? PY : PX, MAXPB);      // provable <=5; clamp=safety
    const int NR  = 7 * PB;

    // Pass-1 row tables: row = ga*PB + bb
    if (t < NR) {
        const int ga = t / PB;
        const int bb = t - ga * PB;
        const int aoff = xf ? 0 : 7;
        const int a0 = s_i0[aoff + ga], a1 = s_i1[aoff + ga];
        const int b  = blo + bb;
        const int adr0 = xf ? (a0 * D + b) : (b * D + a0);
        const int adr1 = xf ? (a1 * D + b) : (b * D + a1);
        s_o0[t] = base + (adr0 << 8);
        s_o1[t] = base + (adr1 << 8);
        s_a0[t] = s_p0[aoff + ga];
        s_a1[t] = s_p1[aoff + ga];
    }
    // Pass-2 per-cell table
    if (t < ROI_GG) {
        const int gi = t / ROI_G, gj = t - gi * ROI_G;
        const int ga = xf ? gi : gj;
        const int gb = xf ? (7 + gj) : gi;
        const int b0 = min(max(s_i0[gb] - blo, 0), PB - 1);
        const int b1 = min(max(s_i1[gb] - blo, 0), PB - 1);
        s_tab[t] = make_float4(s_p0[gb], s_p1[gb],
                               __int_as_float((ga * PB + b0) * RSTRIDE),
                               __int_as_float((ga * PB + b1) * RSTRIDE));
    }
    __syncthreads();

    // ---- pass 1: NR rows x 256 ch, float4 over channels
    const int tot1 = NR << 6;                      // NR * 64 float4 groups
    for (int j = t; j < tot1; j += 512) {
        const int row = j >> 6;
        const int c4  = (j & 63) << 2;
        const float a0 = s_a0[row], a1 = s_a1[row];
        const float4 v0 = *(const float4*)&tfmap[s_o0[row] + c4];
        const float4 v1 = *(const float4*)&tfmap[s_o1[row] + c4];
        float* rp = &s_r[row * RSTRIDE + c4];      // scalar STS, stride-257
        rp[0] = a0 * v0.x + a1 * v1.x;
        rp[1] = a0 * v0.y + a1 * v1.y;
        rp[2] = a0 * v0.z + a1 * v1.z;
        rp[3] = a0 * v0.w + a1 * v1.w;
    }
    __syncthreads();

    // ---- pass 2: slot = t&63 (cell), cgrp = t>>6; two 128-channel halves,
    // each staged in its own s_out half then bulk-stored by the DMA engine.
    const int slot = t & 63;
    const int cgrp = t >> 6;
    float w0 = 0.f, w1 = 0.f; int r0 = 0, r1 = 0;
    if (slot < ROI_GG) {
        const float4 tab = s_tab[slot];
        w0 = tab.x; w1 = tab.y;
        r0 = __float_as_int(tab.z);
        r1 = __float_as_int(tab.w);
    }
    const uint64_t gdst = (uint64_t)(out + (size_t)n * ROI_EPB);

    #pragma unroll
    for (int h = 0; h < 2; ++h) {
        if (slot < ROI_GG) {
            float* so = s_out + h * SOUT_HALF;
            #pragma unroll
            for (int k = 0; k < 16; ++k) {
                const int cl = cgrp + (k << 3);        // 0..127 within half
                const int c  = (h << 7) + cl;          // absolute channel
                so[cl * ROI_GG + slot] = w0 * s_r[r0 + c] + w1 * s_r[r1 + c];
            }
        }
        __syncthreads();
        if (t == 0) {
            asm volatile("fence.proxy.async.shared::cta;" ::: "memory");
            const uint32_t sa = smem_u32(s_out + h * SOUT_HALF);
            asm volatile(
                "cp.async.bulk.global.shared::cta.bulk_group [%0], [%1], %2;"
                :: "l"(gdst + (uint64_t)h * SOUT_BYTES), "r"(sa), "r"(SOUT_BYTES)
                : "memory");
            asm volatile("cp.async.bulk.commit_group;" ::: "memory");
        }
        // no barrier needed after issue: h=1 writes the other buffer
    }
    if (t == 0)
        asm volatile("cp.async.bulk.wait_group 0;" ::: "memory");
}

// ---------------------------------------------------------------------------
extern "C" void kernel_launch(void* const* d_in, const int* in_sizes, int n_in,
                              void* d_out, int out_size) {
    const float* boxes = (const float*)d_in[0];
    const float* f0 = (const float*)d_in[1];
    const float* f1 = (const float*)d_in[2];
    const float* f2 = (const float*)d_in[3];
    const float* f3 = (const float*)d_in[4];
    const float* f4 = (const float*)d_in[5];
    const float* f5 = (const float*)d_in[6];

    const int N = in_sizes[0] / 4;

    // Non-stream API, idempotent, legal during graph capture.
    cudaFuncSetAttribute(roi_kernel,
                         cudaFuncAttributeMaxDynamicSharedMemorySize, DYN_SMEM);

    prep_kernel<<<(TF_TOTAL + 255) / 256, 256>>>(f0, f1, f2, f3, f4, f5);
    roi_kernel<<<N, 512, DYN_SMEM>>>(boxes, (float*)d_out);
}

// round 16
// speedup vs baseline: 1.0995x; 1.0995x over previous
#include <cuda_runtime.h>
#include <cuda_bf16.h>

// N boxes (dynamic), C=256, G=7, fmap dims {38,19,10,5,3,1}
#define ROI_G    7
#define ROI_GG   49
#define ROI_EPB  12544          // 256*49
#define TF_TOTAL 496640         // sum over levels of D*D*256
#define MAXPB    5              // provable bound on short-axis patch size
#define MAXNR    35             // 7*MAXPB
#define RSTRIDE  257            // odd -> conflict-light bank pattern
#define BLOCK_T  784            // 16 channels * 49 cells ; t = c0*49 + g

// Channel-last transposed fmaps: tf[level][x*D+y][c]  (1.99 MB, L2-resident)
static __device__ float tfmap[TF_TOTAL];

__constant__ int c_bnd[7] = {0, 369664, 462080, 487680, 494080, 496384, 496640};
__constant__ int c_Dc[6]  = {38, 19, 10, 5, 3, 1};

// ---------------------------------------------------------------------------
// Prep (R7 orientation — measured faster than scatter-store variant):
// walk [cell][channel]; writes tfmap[idx] coalesced, reads f[c*DD+xy] scattered.
// ---------------------------------------------------------------------------
__global__ void prep_kernel(const float* __restrict__ f0, const float* __restrict__ f1,
                            const float* __restrict__ f2, const float* __restrict__ f3,
                            const float* __restrict__ f4, const float* __restrict__ f5) {
    int idx = blockIdx.x * blockDim.x + threadIdx.x;
    if (idx >= TF_TOTAL) return;
    int l = 0;
    #pragma unroll
    for (int j = 1; j < 6; ++j) l += (idx >= c_bnd[j]) ? 1 : 0;
    const float* f; int D;
    switch (l) {
        case 0: f = f0; D = 38; break;
        case 1: f = f1; D = 19; break;
        case 2: f = f2; D = 10; break;
        case 3: f = f3; D = 5;  break;
        case 4: f = f4; D = 3;  break;
        default:f = f5; D = 1;  break;
    }
    const int local = idx - c_bnd[l];
    const int xy = local >> 8;
    const int c  = local & 255;
    tfmap[idx] = f[c * D * D + xy];
}

// ---------------------------------------------------------------------------
// Main: one block (784 thr) per box. Separable bilinear:
//  pass 1: long-axis lerp from tfmap (coalesced LDG.128) -> s_r[NR][256]
//  pass 2: t = c0*49 + g (c0=0..15, g=cell). Consecutive lanes = consecutive
//          cells -> fully coalesced STG.32, zero lane waste; weights/rows in
//          registers across the 16-channel loop (c = c0 + 16k).
// ---------------------------------------------------------------------------
__global__ __launch_bounds__(BLOCK_T)
void roi_kernel(const float* __restrict__ boxes, float* __restrict__ out) {
    __shared__ float  s_r[MAXNR * RSTRIDE];     // 35.1 KB
    __shared__ int    s_o0[MAXNR], s_o1[MAXNR];
    __shared__ float  s_a0[MAXNR], s_a1[MAXNR];
    __shared__ float4 s_tab[ROI_GG];            // (w0, w1, r0_bits, r1_bits)
    __shared__ int    s_i0[14], s_i1[14];       // [0..6]=x, [7..13]=y
    __shared__ float  s_p0[14], s_p1[14];

    const int n = blockIdx.x;
    const int t = threadIdx.x;

    const float bx1 = __ldg(boxes + 4 * n + 0);
    const float by1 = __ldg(boxes + 4 * n + 1);
    const float bx2 = __ldg(boxes + 4 * n + 2);
    const float by2 = __ldg(boxes + 4 * n + 3);

    const float avg = sqrtf((bx2 - bx1) * (by2 - by1));
    int lvl = (int)floorf(5.0f + log2f(avg));
    lvl = max(0, min(5, lvl));
    const int D    = c_Dc[lvl];
    const int base = c_bnd[lvl];

    // 14 sample sets: floor/ceil indices + proportion weights (ref-exact)
    if (t < 14) {
        const int axis = t / 7, g = t - axis * 7;
        const float lo = axis ? by1 : bx1;
        const float hi = axis ? by2 : bx2;
        const float fr = fminf(fmaxf(lo + ((float)g * (hi - lo)) / 6.0f, 0.0f), 1.0f);
        const float u  = fr * (float)(D - 1);
        const float u0 = floorf(u);
        s_i0[t] = (int)u0;
        s_i1[t] = (int)ceilf(u);
        const float p0 = 1.0f - (u - u0);       // ddx==1 convention of ref
        s_p0[t] = p0;
        s_p1[t] = 1.0f - p0;
    }
    __syncthreads();

    // Meta from smem broadcasts (every thread computes it; no serial stage)
    const int PX  = s_i1[6]  - s_i0[0] + 1;
    const int PY  = s_i1[13] - s_i0[7] + 1;
    const int xf  = (PX >= PY) ? 1 : 0;         // lerp longer axis first
    const int blo = xf ? s_i0[7] : s_i0[0];     // short-axis patch start
    const int PB  = min(xf ? PY : PX, MAXPB);   // provable <=5; clamp=safety
    const int NR  = 7 * PB;

    // Pass-1 row tables: row = ga*PB + bb
    if (t < NR) {
        const int ga = t / PB;
        const int bb = t - ga * PB;
        const int aoff = xf ? 0 : 7;
        const int a0 = s_i0[aoff + ga], a1 = s_i1[aoff + ga];
        const int b  = blo + bb;
        const int adr0 = xf ? (a0 * D + b) : (b * D + a0);
        const int adr1 = xf ? (a1 * D + b) : (b * D + a1);
        s_o0[t] = base + (adr0 << 8);
        s_o1[t] = base + (adr1 << 8);
        s_a0[t] = s_p0[aoff + ga];
        s_a1[t] = s_p1[aoff + ga];
    }
    // Pass-2 per-cell table
    if (t < ROI_GG) {
        const int gi = t / ROI_G, gj = t - gi * ROI_G;
        const int ga = xf ? gi : gj;
        const int gb = xf ? (7 + gj) : gi;
        const int b0 = min(max(s_i0[gb] - blo, 0), PB - 1);
        const int b1 = min(max(s_i1[gb] - blo, 0), PB - 1);
        s_tab[t] = make_float4(s_p0[gb], s_p1[gb],
                               __int_as_float((ga * PB + b0) * RSTRIDE),
                               __int_as_float((ga * PB + b1) * RSTRIDE));
    }
    __syncthreads();

    // ---- pass 1: NR rows x 256 ch, float4 over channels (<=3 iters/thread)
    const int tot1 = NR << 6;                   // NR * 64 float4 groups
    for (int j = t; j < tot1; j += BLOCK_T) {
        const int row = j >> 6;
        const int c4  = (j & 63) << 2;
        const float a0 = s_a0[row], a1 = s_a1[row];
        const float4 v0 = *(const float4*)&tfmap[s_o0[row] + c4];
        const float4 v1 = *(const float4*)&tfmap[s_o1[row] + c4];
        float* rp = &s_r[row * RSTRIDE + c4];   // scalar STS, stride-257
        rp[0] = a0 * v0.x + a1 * v1.x;
        rp[1] = a0 * v0.y + a1 * v1.y;
        rp[2] = a0 * v0.z + a1 * v1.z;
        rp[3] = a0 * v0.w + a1 * v1.w;
    }
    __syncthreads();

    // ---- pass 2: t = c0*49 + g; 16 channels per thread (c = c0 + 16k).
    // Stores: consecutive lanes = consecutive g -> coalesced STG.32.
    const int c0 = t / ROI_GG;                  // 0..15
    const int g  = t - c0 * ROI_GG;             // 0..48
    const float4 tab = s_tab[g];
    const float w0 = tab.x, w1 = tab.y;
    const int r0 = __float_as_int(tab.z);
    const int r1 = __float_as_int(tab.w);
    float* outn = out + (size_t)n * ROI_EPB + g;

    #pragma unroll
    for (int k = 0; k < 16; ++k) {
        const int c = c0 + (k << 4);            // covers 0..255 exactly
        outn[c * ROI_GG] = w0 * s_r[r0 + c] + w1 * s_r[r1 + c];
    }
}

// ---------------------------------------------------------------------------
extern "C" void kernel_launch(void* const* d_in, const int* in_sizes, int n_in,
                              void* d_out, int out_size) {
    const float* boxes = (const float*)d_in[0];
    const float* f0 = (const float*)d_in[1];
    const float* f1 = (const float*)d_in[2];
    const float* f2 = (const float*)d_in[3];
    const float* f3 = (const float*)d_in[4];
    const float* f4 = (const float*)d_in[5];
    const float* f5 = (const float*)d_in[6];

    const int N = in_sizes[0] / 4;

    prep_kernel<<<(TF_TOTAL + 255) / 256, 256>>>(f0, f1, f2, f3, f4, f5);
    roi_kernel<<<N, BLOCK_T>>>(boxes, (float*)d_out);
}